// round 11
// baseline (speedup 1.0000x reference)
#include <cuda_runtime.h>
#include <cuda_fp16.h>

#define NN 100000
#define NE 1600000
#define NF 128
#define NH 64
#define NC 16

// ---------------- scratch (static device globals) ----------------
__device__ int    g_deg[2 * NN];            // [0,NN): out-degree, [NN,2NN): in-degree
__device__ int    g_part[256];              // scan partials (196 used)
__device__ int    g_rowptr[NN + 1];
__device__ int    g_cursor[NN];
__device__ int    g_col[NE];                // src node per CSR slot
__device__ __half g_h1h[(size_t)NN * NH];   // (x@W1)*norm_src, fp16
__device__ float  g_h2[(size_t)NN * NC];    // (r@W2)*norm_src

#define ADD2(acc, v) asm("add.rn.f32x2 %0, %0, %1;" : "+l"(acc) : "l"(v))
#define CP16(dst, src, sz) \
    asm volatile("cp.async.cg.shared.global [%0], [%1], 16, %2;" \
                 :: "r"(dst), "l"(src), "r"(sz))

__device__ __forceinline__ unsigned smem_u32(const void* p) {
    return (unsigned)__cvta_generic_to_shared(p);
}

// ---------------- in-degree histogram, 4 edges/thread ----------------
__global__ void k_hist(const int* __restrict__ dst) {
    int i = blockIdx.x * blockDim.x + threadIdx.x;
    if (i * 4 < NE) {
        int4 d = *(const int4*)&dst[i * 4];
        atomicAdd(&g_deg[NN + d.x], 1);
        atomicAdd(&g_deg[NN + d.y], 1);
        atomicAdd(&g_deg[NN + d.z], 1);
        atomicAdd(&g_deg[NN + d.w], 1);
    }
}

// ---------------- scan phase A: 196 blocks x 512 nodes -> block sums ----------------
__global__ void __launch_bounds__(256) k_scanA() {
    __shared__ int sh[256];
    const int t = threadIdx.x;
    int i0 = blockIdx.x * 512 + 2 * t;
    int s = 0;
    if (i0 < NN) s += g_deg[NN + i0];
    if (i0 + 1 < NN) s += g_deg[NN + i0 + 1];
    sh[t] = s;
    __syncthreads();
    for (int off = 128; off > 0; off >>= 1) {
        if (t < off) sh[t] += sh[t + off];
        __syncthreads();
    }
    if (t == 0) g_part[blockIdx.x] = sh[0];
    if (t == 1 && blockIdx.x == 0) g_rowptr[NN] = NE;
}

// ---------------- scan phase C: every block scans partials + local scan ----------------
__global__ void __launch_bounds__(256) k_scanC() {
    __shared__ int part[256];
    __shared__ int loc[256];
    const int t = threadIdx.x;
    const int b = blockIdx.x;

    part[t] = (t < 196) ? g_part[t] : 0;
    __syncthreads();
    for (int off = 1; off < 256; off <<= 1) {
        int u = (t >= off) ? part[t - off] : 0;
        __syncthreads();
        part[t] += u;
        __syncthreads();
    }
    int offset = (b > 0) ? part[b - 1] : 0;

    int i0 = b * 512 + 2 * t;
    int d0 = (i0 < NN) ? g_deg[NN + i0] : 0;
    int d1 = (i0 + 1 < NN) ? g_deg[NN + i0 + 1] : 0;
    loc[t] = d0 + d1;
    __syncthreads();
    for (int off = 1; off < 256; off <<= 1) {
        int u = (t >= off) ? loc[t - off] : 0;
        __syncthreads();
        loc[t] += u;
        __syncthreads();
    }
    int excl = offset + ((t > 0) ? loc[t - 1] : 0);
    if (i0 < NN)     { g_rowptr[i0] = excl;          g_cursor[i0] = excl; }
    if (i0 + 1 < NN) { g_rowptr[i0 + 1] = excl + d0; g_cursor[i0 + 1] = excl + d0; }
}

// ---------------- fill CSR + out-degree ----------------
__global__ void k_fill(const int* __restrict__ src, const int* __restrict__ dst) {
    int e = blockIdx.x * blockDim.x + threadIdx.x;
    if (e < NE) {
        int d = dst[e];
        int s = src[e];
        int pos = atomicAdd(&g_cursor[d], 1);
        g_col[pos] = s;
        atomicAdd(&g_deg[s], 1);
    }
}

// ---------------- layer-1 GEMM: h1h = fp16((x @ W1) * norm_src) ----------------
// 512 nodes x 64 feats/block, 512 threads, 8x8 per thread, cp.async 2-stage.
// 88KB dynamic smem; 16 warps/SM for latency hiding.
#define XS_STRIDE 20
#define XS_ROWS 512
#define XS_BUF (XS_ROWS * XS_STRIDE)
#define WS_OFF (2 * XS_BUF)
#define GEMM_SMEM ((2 * XS_BUF + 2 * 16 * 64) * 4)

__global__ void __launch_bounds__(512) k_gemm1(const float* __restrict__ x,
                                               const float* __restrict__ W1) {
    extern __shared__ __align__(16) float sm[];
    // Xs[buf][node][20] at sm; Ws[buf][16][64] at sm + WS_OFF
    const int tid = threadIdx.x;
    const int tx = tid & 7;     // feat group (8 feats)
    const int ty = tid >> 3;    // node group (8 nodes), 0..63
    const int n0 = blockIdx.x * XS_ROWS;
    const int wkk = tid >> 4, wf4 = tid & 15;   // threads 0..255 load W

    unsigned long long accp[8][4];
    #pragma unroll
    for (int i = 0; i < 8; i++)
        #pragma unroll
        for (int j = 0; j < 4; j++) accp[i][j] = 0ull;

    auto issue = [&](int kc) {
        float* Xb = sm + (kc & 1) * XS_BUF;
        #pragma unroll
        for (int it = 0; it < 4; it++) {
            int i = tid + it * 512;          // 0..2047 chunk index
            int nl = i >> 2, f4 = i & 3;
            int n = n0 + nl;
            unsigned d = smem_u32(Xb + nl * XS_STRIDE + f4 * 4);
            const float* s = &x[(size_t)n * NF + kc * 16 + f4 * 4];
            CP16(d, s, (n < NN) ? 16 : 0);
        }
        if (tid < 256) {
            float* Wb = sm + WS_OFF + (kc & 1) * (16 * 64);
            unsigned dw = smem_u32(Wb + wkk * 64 + wf4 * 4);
            const float* sw = &W1[(size_t)(kc * 16 + wkk) * NH + wf4 * 4];
            CP16(dw, sw, 16);
        }
        asm volatile("cp.async.commit_group;");
    };

    issue(0);
    for (int kc = 0; kc < NF / 16; kc++) {
        if (kc + 1 < NF / 16) {
            issue(kc + 1);
            asm volatile("cp.async.wait_group 1;");
        } else {
            asm volatile("cp.async.wait_group 0;");
        }
        __syncthreads();
        const float* Xb = sm + (kc & 1) * XS_BUF;
        const float* Wb = sm + WS_OFF + (kc & 1) * (16 * 64);

        #pragma unroll
        for (int kk = 0; kk < 16; kk++) {
            float av[8];
            #pragma unroll
            for (int i = 0; i < 8; i++) av[i] = Xb[(ty * 8 + i) * XS_STRIDE + kk];
            ulonglong2 w0 = *(const ulonglong2*)(Wb + kk * 64 + tx * 8);
            ulonglong2 w1 = *(const ulonglong2*)(Wb + kk * 64 + tx * 8 + 4);
            unsigned long long bp[4] = {w0.x, w0.y, w1.x, w1.y};
            #pragma unroll
            for (int i = 0; i < 8; i++) {
                unsigned long long ad;
                asm("mov.b64 %0, {%1, %1};" : "=l"(ad) : "f"(av[i]));
                #pragma unroll
                for (int jj = 0; jj < 4; jj++)
                    asm("fma.rn.f32x2 %0, %1, %2, %0;"
                        : "+l"(accp[i][jj]) : "l"(ad), "l"(bp[jj]));
            }
        }
        __syncthreads();
    }

    #pragma unroll
    for (int i = 0; i < 8; i++) {
        int n = n0 + ty * 8 + i;
        if (n < NN) {
            float s = rsqrtf((float)max(g_deg[n], 1));
            __half2 h[4];
            #pragma unroll
            for (int jj = 0; jj < 4; jj++) {
                float lo, hi;
                asm("mov.b64 {%0, %1}, %2;" : "=f"(lo), "=f"(hi) : "l"(accp[i][jj]));
                h[jj] = __floats2half2_rn(lo * s, hi * s);
            }
            *(uint4*)&g_h1h[(size_t)n * NH + tx * 8] = *(uint4*)h;
        }
    }
}

// ---------------- fused: gather1 + relu + hidden GEMM -> h2 ----------------
__global__ void __launch_bounds__(256) k_gather1h(const float* __restrict__ b1,
                                                  const float* __restrict__ W2) {
    __shared__ __align__(16) float Rs[32][NH];      // 8KB
    __shared__ __align__(16) float W2s[NH * NC];    // 4KB

    const int tid = threadIdx.x;
    const int nl = tid >> 3;                 // node local 0..31
    const int lane = tid & 7;
    const int g = blockIdx.x * 32 + nl;

    *(float4*)&W2s[tid * 4] = *(const float4*)&W2[tid * 4];

    const int s0 = g_rowptr[g];
    const int s1 = g_rowptr[g + 1];
    float acc[8] = {};

    int j = s0;
    for (; j + 8 <= s1; j += 8) {
        int c[8];
        #pragma unroll
        for (int q = 0; q < 8; q++) c[q] = __ldg(&g_col[j + q]);
        #pragma unroll
        for (int q = 0; q < 8; q++) {
            uint4 v = *(const uint4*)&g_h1h[(size_t)c[q] * NH + lane * 8];
            const __half2* hv = (const __half2*)&v;
            #pragma unroll
            for (int p = 0; p < 4; p++) {
                float2 f = __half22float2(hv[p]);
                acc[2 * p] += f.x;
                acc[2 * p + 1] += f.y;
            }
        }
    }
    for (; j < s1; j++) {
        int c = __ldg(&g_col[j]);
        uint4 v = *(const uint4*)&g_h1h[(size_t)c * NH + lane * 8];
        const __half2* hv = (const __half2*)&v;
        #pragma unroll
        for (int p = 0; p < 4; p++) {
            float2 f = __half22float2(hv[p]);
            acc[2 * p] += f.x;
            acc[2 * p + 1] += f.y;
        }
    }

    float nd = rsqrtf((float)max(s1 - s0, 1));
    float4 bb0 = *(const float4*)&b1[lane * 8];
    float4 bb1 = *(const float4*)&b1[lane * 8 + 4];
    float bv[8] = {bb0.x, bb0.y, bb0.z, bb0.w, bb1.x, bb1.y, bb1.z, bb1.w};
    #pragma unroll
    for (int q = 0; q < 8; q++)
        Rs[nl][lane * 8 + q] = fmaxf(fmaf(acc[q], nd, bv[q]), 0.f);
    __syncthreads();

    const int c0 = lane * 2;
    float a0 = 0.f, a1 = 0.f;
    #pragma unroll
    for (int k = 0; k < NH; k++) {
        float rv = Rs[nl][k];
        float2 w = *(const float2*)&W2s[k * NC + c0];
        a0 = fmaf(rv, w.x, a0);
        a1 = fmaf(rv, w.y, a1);
    }
    float ns = rsqrtf((float)max(g_deg[g], 1));
    *(float2*)&g_h2[(size_t)g * NC + c0] = make_float2(a0 * ns, a1 * ns);
}

// ---------------- layer-2 gather + log_softmax fused ----------------
__global__ void __launch_bounds__(256) k_gather2(const float* __restrict__ b2,
                                                 float* __restrict__ out) {
    int g0 = blockIdx.x * 64 + (threadIdx.x >> 2);
    const bool valid = (g0 < NN);
    const int g = valid ? g0 : (NN - 1);
    const int lane = threadIdx.x & 3;

    const int s0 = g_rowptr[g];
    const int s1 = g_rowptr[g + 1];
    unsigned long long acc0 = 0ull, acc1 = 0ull;

    int j = s0;
    for (; j + 8 <= s1; j += 8) {
        int c[8];
        #pragma unroll
        for (int q = 0; q < 8; q++) c[q] = __ldg(&g_col[j + q]);
        #pragma unroll
        for (int q = 0; q < 8; q++) {
            ulonglong2 v = *(const ulonglong2*)&g_h2[(size_t)c[q] * NC + lane * 4];
            ADD2(acc0, v.x);
            ADD2(acc1, v.y);
        }
    }
    for (; j < s1; j++) {
        int c = __ldg(&g_col[j]);
        ulonglong2 v = *(const ulonglong2*)&g_h2[(size_t)c * NC + lane * 4];
        ADD2(acc0, v.x);
        ADD2(acc1, v.y);
    }

    float nd = rsqrtf((float)max(s1 - s0, 1));
    float v[4];
    asm("mov.b64 {%0, %1}, %2;" : "=f"(v[0]), "=f"(v[1]) : "l"(acc0));
    asm("mov.b64 {%0, %1}, %2;" : "=f"(v[2]), "=f"(v[3]) : "l"(acc1));
    float4 bb = *(const float4*)&b2[lane * 4];
    v[0] = fmaf(v[0], nd, bb.x);
    v[1] = fmaf(v[1], nd, bb.y);
    v[2] = fmaf(v[2], nd, bb.z);
    v[3] = fmaf(v[3], nd, bb.w);

    float mloc = fmaxf(fmaxf(v[0], v[1]), fmaxf(v[2], v[3]));
    mloc = fmaxf(mloc, __shfl_xor_sync(0xFFFFFFFFu, mloc, 1, 4));
    mloc = fmaxf(mloc, __shfl_xor_sync(0xFFFFFFFFu, mloc, 2, 4));

    float sl = __expf(v[0] - mloc) + __expf(v[1] - mloc) +
               __expf(v[2] - mloc) + __expf(v[3] - mloc);
    sl += __shfl_xor_sync(0xFFFFFFFFu, sl, 1, 4);
    sl += __shfl_xor_sync(0xFFFFFFFFu, sl, 2, 4);
    float l = mloc + __logf(sl);

    if (valid)
        *(float4*)&out[(size_t)g * NC + lane * 4] =
            make_float4(v[0] - l, v[1] - l, v[2] - l, v[3] - l);
}

// ---------------- launch ----------------
extern "C" void kernel_launch(void* const* d_in, const int* in_sizes, int n_in,
                              void* d_out, int out_size) {
    const float* x   = (const float*)d_in[0];
    const int*   src = (const int*)d_in[1];
    const int*   dst = (const int*)d_in[2];
    const float* W1  = (const float*)d_in[3];
    const float* b1  = (const float*)d_in[4];
    const float* W2  = (const float*)d_in[5];
    const float* b2  = (const float*)d_in[6];
    float* out = (float*)d_out;

    cudaFuncSetAttribute(k_gemm1, cudaFuncAttributeMaxDynamicSharedMemorySize,
                         GEMM_SMEM);

    void* pdeg;
    cudaGetSymbolAddress(&pdeg, g_deg);
    cudaMemsetAsync(pdeg, 0, (size_t)2 * NN * sizeof(int));

    k_hist<<<(NE / 4 + 255) / 256, 256>>>(dst);
    k_scanA<<<196, 256>>>();
    k_scanC<<<196, 256>>>();
    k_fill<<<(NE + 255) / 256, 256>>>(src, dst);
    k_gemm1<<<(NN + 511) / 512, 512, GEMM_SMEM>>>(x, W1);
    k_gather1h<<<NN / 32, 256>>>(b1, W2);
    k_gather2<<<(NN + 63) / 64, 256>>>(b2, out);
}

// round 12
// speedup vs baseline: 1.1116x; 1.1116x over previous
#include <cuda_runtime.h>
#include <cuda_fp16.h>

#define NN 100000
#define NE 1600000
#define NF 128
#define NH 64
#define NC 16

// ---------------- scratch (static device globals) ----------------
__device__ int    g_deg[2 * NN];            // [0,NN): out-degree, [NN,2NN): in-degree
__device__ int    g_part[256];              // scan partials (196 used)
__device__ int    g_rowptr[NN + 1];
__device__ int    g_cursor[NN];
__device__ int    g_col[NE];                // src node per CSR slot
__device__ float  g_ns[NN];                 // rsqrt(max(outdeg,1))
__device__ __half g_h1h[(size_t)NN * NH];   // x@W1 (UNscaled), fp16
__device__ float  g_h2[(size_t)NN * NC];    // (r@W2)*norm_src

#define ADD2(acc, v) asm("add.rn.f32x2 %0, %0, %1;" : "+l"(acc) : "l"(v))
#define CP16(dst, src, sz) \
    asm volatile("cp.async.cg.shared.global [%0], [%1], 16, %2;" \
                 :: "r"(dst), "l"(src), "r"(sz))

__device__ __forceinline__ unsigned smem_u32(const void* p) {
    return (unsigned)__cvta_generic_to_shared(p);
}

// ---------------- in-degree histogram, 4 edges/thread ----------------
__global__ void k_hist(const int* __restrict__ dst) {
    int i = blockIdx.x * blockDim.x + threadIdx.x;
    if (i * 4 < NE) {
        int4 d = *(const int4*)&dst[i * 4];
        atomicAdd(&g_deg[NN + d.x], 1);
        atomicAdd(&g_deg[NN + d.y], 1);
        atomicAdd(&g_deg[NN + d.z], 1);
        atomicAdd(&g_deg[NN + d.w], 1);
    }
}

// ---------------- scan phase A ----------------
__global__ void __launch_bounds__(256) k_scanA() {
    __shared__ int sh[256];
    const int t = threadIdx.x;
    int i0 = blockIdx.x * 512 + 2 * t;
    int s = 0;
    if (i0 < NN) s += g_deg[NN + i0];
    if (i0 + 1 < NN) s += g_deg[NN + i0 + 1];
    sh[t] = s;
    __syncthreads();
    for (int off = 128; off > 0; off >>= 1) {
        if (t < off) sh[t] += sh[t + off];
        __syncthreads();
    }
    if (t == 0) g_part[blockIdx.x] = sh[0];
    if (t == 1 && blockIdx.x == 0) g_rowptr[NN] = NE;
}

// ---------------- scan phase C ----------------
__global__ void __launch_bounds__(256) k_scanC() {
    __shared__ int part[256];
    __shared__ int loc[256];
    const int t = threadIdx.x;
    const int b = blockIdx.x;

    part[t] = (t < 196) ? g_part[t] : 0;
    __syncthreads();
    for (int off = 1; off < 256; off <<= 1) {
        int u = (t >= off) ? part[t - off] : 0;
        __syncthreads();
        part[t] += u;
        __syncthreads();
    }
    int offset = (b > 0) ? part[b - 1] : 0;

    int i0 = b * 512 + 2 * t;
    int d0 = (i0 < NN) ? g_deg[NN + i0] : 0;
    int d1 = (i0 + 1 < NN) ? g_deg[NN + i0 + 1] : 0;
    loc[t] = d0 + d1;
    __syncthreads();
    for (int off = 1; off < 256; off <<= 1) {
        int u = (t >= off) ? loc[t - off] : 0;
        __syncthreads();
        loc[t] += u;
        __syncthreads();
    }
    int excl = offset + ((t > 0) ? loc[t - 1] : 0);
    if (i0 < NN)     { g_rowptr[i0] = excl;          g_cursor[i0] = excl; }
    if (i0 + 1 < NN) { g_rowptr[i0 + 1] = excl + d0; g_cursor[i0 + 1] = excl + d0; }
}

// ---------------- fill CSR + out-degree, 4 edges/thread ----------------
__global__ void k_fill(const int* __restrict__ src, const int* __restrict__ dst) {
    int i = blockIdx.x * blockDim.x + threadIdx.x;
    if (i * 4 < NE) {
        int4 s = *(const int4*)&src[i * 4];
        int4 d = *(const int4*)&dst[i * 4];
        int p0 = atomicAdd(&g_cursor[d.x], 1);
        int p1 = atomicAdd(&g_cursor[d.y], 1);
        int p2 = atomicAdd(&g_cursor[d.z], 1);
        int p3 = atomicAdd(&g_cursor[d.w], 1);
        g_col[p0] = s.x;
        g_col[p1] = s.y;
        g_col[p2] = s.z;
        g_col[p3] = s.w;
        atomicAdd(&g_deg[s.x], 1);
        atomicAdd(&g_deg[s.y], 1);
        atomicAdd(&g_deg[s.z], 1);
        atomicAdd(&g_deg[s.w], 1);
    }
}

// ---------------- norm_src precompute ----------------
__global__ void k_ns() {
    int i = blockIdx.x * blockDim.x + threadIdx.x;
    if (i < NN) g_ns[i] = rsqrtf((float)max(g_deg[i], 1));
}

// ---------------- layer-1 GEMM: h1h = fp16(x @ W1)  (UNscaled) ----------------
// R10-exact structure: 256 nodes x 64 feats/block, cp.async double-buffered.
__global__ void __launch_bounds__(256) k_gemm1(const float* __restrict__ x,
                                               const float* __restrict__ W1) {
    __shared__ __align__(16) float Xs[2][256][20];
    __shared__ __align__(16) float Ws[2][16][64];

    const int tid = threadIdx.x;
    const int tx = tid & 7;
    const int ty = tid >> 3;
    const int n0 = blockIdx.x * 256;
    const int wkk = tid >> 4, wf4 = tid & 15;

    unsigned long long accp[8][4];
    #pragma unroll
    for (int i = 0; i < 8; i++)
        #pragma unroll
        for (int j = 0; j < 4; j++) accp[i][j] = 0ull;

    auto issue = [&](int kc) {
        int buf = kc & 1;
        #pragma unroll
        for (int it = 0; it < 4; it++) {
            int i = tid + it * 256;
            int nl = i >> 2, f4 = i & 3;
            int n = n0 + nl;
            unsigned d = smem_u32(&Xs[buf][nl][f4 * 4]);
            const float* s = &x[(size_t)n * NF + kc * 16 + f4 * 4];
            CP16(d, s, (n < NN) ? 16 : 0);
        }
        unsigned dw = smem_u32(&Ws[buf][wkk][wf4 * 4]);
        const float* sw = &W1[(size_t)(kc * 16 + wkk) * NH + wf4 * 4];
        CP16(dw, sw, 16);
        asm volatile("cp.async.commit_group;");
    };

    issue(0);
    for (int kc = 0; kc < NF / 16; kc++) {
        if (kc + 1 < NF / 16) {
            issue(kc + 1);
            asm volatile("cp.async.wait_group 1;");
        } else {
            asm volatile("cp.async.wait_group 0;");
        }
        __syncthreads();
        const int buf = kc & 1;

        #pragma unroll
        for (int kk = 0; kk < 16; kk++) {
            float av[8];
            #pragma unroll
            for (int i = 0; i < 8; i++) av[i] = Xs[buf][ty * 8 + i][kk];
            ulonglong2 w0 = *(const ulonglong2*)&Ws[buf][kk][tx * 8];
            ulonglong2 w1 = *(const ulonglong2*)&Ws[buf][kk][tx * 8 + 4];
            unsigned long long bp[4] = {w0.x, w0.y, w1.x, w1.y};
            #pragma unroll
            for (int i = 0; i < 8; i++) {
                unsigned long long ad;
                asm("mov.b64 %0, {%1, %1};" : "=l"(ad) : "f"(av[i]));
                #pragma unroll
                for (int jj = 0; jj < 4; jj++)
                    asm("fma.rn.f32x2 %0, %1, %2, %0;"
                        : "+l"(accp[i][jj]) : "l"(ad), "l"(bp[jj]));
            }
        }
        __syncthreads();
    }

    #pragma unroll
    for (int i = 0; i < 8; i++) {
        int n = n0 + ty * 8 + i;
        if (n < NN) {
            __half2 h[4];
            #pragma unroll
            for (int jj = 0; jj < 4; jj++) {
                float lo, hi;
                asm("mov.b64 {%0, %1}, %2;" : "=f"(lo), "=f"(hi) : "l"(accp[i][jj]));
                h[jj] = __floats2half2_rn(lo, hi);
            }
            *(uint4*)&g_h1h[(size_t)n * NH + tx * 8] = *(uint4*)h;
        }
    }
}

// ---------------- fused: gather1 (with per-src ns) + relu + hidden GEMM ----------------
__global__ void __launch_bounds__(256) k_gather1h(const float* __restrict__ b1,
                                                  const float* __restrict__ W2) {
    __shared__ __align__(16) float Rs[32][NH];
    __shared__ __align__(16) float W2s[NH * NC];

    const int tid = threadIdx.x;
    const int nl = tid >> 3;
    const int lane = tid & 7;
    const int g = blockIdx.x * 32 + nl;

    *(float4*)&W2s[tid * 4] = *(const float4*)&W2[tid * 4];

    const int s0 = g_rowptr[g];
    const int s1 = g_rowptr[g + 1];
    float acc[8] = {};

    int j = s0;
    for (; j + 8 <= s1; j += 8) {
        int c[8];
        #pragma unroll
        for (int q = 0; q < 8; q++) c[q] = __ldg(&g_col[j + q]);
        float nsv[8];
        #pragma unroll
        for (int q = 0; q < 8; q++) nsv[q] = __ldg(&g_ns[c[q]]);
        #pragma unroll
        for (int q = 0; q < 8; q++) {
            uint4 v = *(const uint4*)&g_h1h[(size_t)c[q] * NH + lane * 8];
            const __half2* hv = (const __half2*)&v;
            #pragma unroll
            for (int p = 0; p < 4; p++) {
                float2 f = __half22float2(hv[p]);
                acc[2 * p]     = fmaf(f.x, nsv[q], acc[2 * p]);
                acc[2 * p + 1] = fmaf(f.y, nsv[q], acc[2 * p + 1]);
            }
        }
    }
    for (; j < s1; j++) {
        int c = __ldg(&g_col[j]);
        float nsv = __ldg(&g_ns[c]);
        uint4 v = *(const uint4*)&g_h1h[(size_t)c * NH + lane * 8];
        const __half2* hv = (const __half2*)&v;
        #pragma unroll
        for (int p = 0; p < 4; p++) {
            float2 f = __half22float2(hv[p]);
            acc[2 * p]     = fmaf(f.x, nsv, acc[2 * p]);
            acc[2 * p + 1] = fmaf(f.y, nsv, acc[2 * p + 1]);
        }
    }

    float nd = rsqrtf((float)max(s1 - s0, 1));
    float4 bb0 = *(const float4*)&b1[lane * 8];
    float4 bb1 = *(const float4*)&b1[lane * 8 + 4];
    float bv[8] = {bb0.x, bb0.y, bb0.z, bb0.w, bb1.x, bb1.y, bb1.z, bb1.w};
    #pragma unroll
    for (int q = 0; q < 8; q++)
        Rs[nl][lane * 8 + q] = fmaxf(fmaf(acc[q], nd, bv[q]), 0.f);
    __syncthreads();

    const int c0 = lane * 2;
    float a0 = 0.f, a1 = 0.f;
    #pragma unroll
    for (int k = 0; k < NH; k++) {
        float rv = Rs[nl][k];
        float2 w = *(const float2*)&W2s[k * NC + c0];
        a0 = fmaf(rv, w.x, a0);
        a1 = fmaf(rv, w.y, a1);
    }
    float ns = g_ns[g];
    *(float2*)&g_h2[(size_t)g * NC + c0] = make_float2(a0 * ns, a1 * ns);
}

// ---------------- layer-2 gather + log_softmax fused ----------------
__global__ void __launch_bounds__(256) k_gather2(const float* __restrict__ b2,
                                                 float* __restrict__ out) {
    int g0 = blockIdx.x * 64 + (threadIdx.x >> 2);
    const bool valid = (g0 < NN);
    const int g = valid ? g0 : (NN - 1);
    const int lane = threadIdx.x & 3;

    const int s0 = g_rowptr[g];
    const int s1 = g_rowptr[g + 1];
    unsigned long long acc0 = 0ull, acc1 = 0ull;

    int j = s0;
    for (; j + 8 <= s1; j += 8) {
        int c[8];
        #pragma unroll
        for (int q = 0; q < 8; q++) c[q] = __ldg(&g_col[j + q]);
        #pragma unroll
        for (int q = 0; q < 8; q++) {
            ulonglong2 v = *(const ulonglong2*)&g_h2[(size_t)c[q] * NC + lane * 4];
            ADD2(acc0, v.x);
            ADD2(acc1, v.y);
        }
    }
    for (; j < s1; j++) {
        int c = __ldg(&g_col[j]);
        ulonglong2 v = *(const ulonglong2*)&g_h2[(size_t)c * NC + lane * 4];
        ADD2(acc0, v.x);
        ADD2(acc1, v.y);
    }

    float nd = rsqrtf((float)max(s1 - s0, 1));
    float v[4];
    asm("mov.b64 {%0, %1}, %2;" : "=f"(v[0]), "=f"(v[1]) : "l"(acc0));
    asm("mov.b64 {%0, %1}, %2;" : "=f"(v[2]), "=f"(v[3]) : "l"(acc1));
    float4 bb = *(const float4*)&b2[lane * 4];
    v[0] = fmaf(v[0], nd, bb.x);
    v[1] = fmaf(v[1], nd, bb.y);
    v[2] = fmaf(v[2], nd, bb.z);
    v[3] = fmaf(v[3], nd, bb.w);

    float mloc = fmaxf(fmaxf(v[0], v[1]), fmaxf(v[2], v[3]));
    mloc = fmaxf(mloc, __shfl_xor_sync(0xFFFFFFFFu, mloc, 1, 4));
    mloc = fmaxf(mloc, __shfl_xor_sync(0xFFFFFFFFu, mloc, 2, 4));

    float sl = __expf(v[0] - mloc) + __expf(v[1] - mloc) +
               __expf(v[2] - mloc) + __expf(v[3] - mloc);
    sl += __shfl_xor_sync(0xFFFFFFFFu, sl, 1, 4);
    sl += __shfl_xor_sync(0xFFFFFFFFu, sl, 2, 4);
    float l = mloc + __logf(sl);

    if (valid)
        *(float4*)&out[(size_t)g * NC + lane * 4] =
            make_float4(v[0] - l, v[1] - l, v[2] - l, v[3] - l);
}

// ---------------- launch: fork CSR build onto a side stream ----------------
extern "C" void kernel_launch(void* const* d_in, const int* in_sizes, int n_in,
                              void* d_out, int out_size) {
    const float* x   = (const float*)d_in[0];
    const int*   src = (const int*)d_in[1];
    const int*   dst = (const int*)d_in[2];
    const float* W1  = (const float*)d_in[3];
    const float* b1  = (const float*)d_in[4];
    const float* W2  = (const float*)d_in[5];
    const float* b2  = (const float*)d_in[6];
    float* out = (float*)d_out;

    // host-side objects only; intentionally not destroyed (kernel_launch is
    // invoked only a handful of times, and destroying a stream mid-capture
    // would invalidate the graph).
    cudaStream_t s1;
    cudaStreamCreateWithFlags(&s1, cudaStreamNonBlocking);
    cudaEvent_t evF, evJ;
    cudaEventCreateWithFlags(&evF, cudaEventDisableTiming);
    cudaEventCreateWithFlags(&evJ, cudaEventDisableTiming);

    void* pdeg;
    cudaGetSymbolAddress(&pdeg, g_deg);

    // fork: CSR chain on s1
    cudaEventRecord(evF, 0);
    cudaStreamWaitEvent(s1, evF, 0);
    cudaMemsetAsync(pdeg, 0, (size_t)2 * NN * sizeof(int), s1);
    k_hist<<<(NE / 4 + 255) / 256, 256, 0, s1>>>(dst);
    k_scanA<<<196, 256, 0, s1>>>();
    k_scanC<<<196, 256, 0, s1>>>();
    k_fill<<<(NE / 4 + 255) / 256, 256, 0, s1>>>(src, dst);
    k_ns<<<(NN + 255) / 256, 256, 0, s1>>>();
    cudaEventRecord(evJ, s1);

    // concurrent: dense GEMM on the main (captured) stream
    k_gemm1<<<(NN + 255) / 256, 256>>>(x, W1);

    // join, then gather chain
    cudaStreamWaitEvent(0, evJ, 0);
    k_gather1h<<<NN / 32, 256>>>(b1, W2);
    k_gather2<<<(NN + 63) / 64, 256>>>(b2, out);
}

// round 13
// speedup vs baseline: 1.2119x; 1.0903x over previous
#include <cuda_runtime.h>
#include <cuda_fp16.h>

#define NN 100000
#define NE 1600000
#define NF 128
#define NH 64
#define NC 16

// ---------------- scratch (static device globals) ----------------
__device__ int    g_deg[2 * NN];            // [0,NN): out-degree, [NN,2NN): in-degree
__device__ int    g_part[256];              // scan partials (196 used)
__device__ int    g_rowptr[NN + 1];
__device__ int    g_cursor[NN];
__device__ int    g_col[NE];                // src node per CSR slot
__device__ float  g_ns[NN];                 // rsqrt(max(outdeg,1))
__device__ __half g_h1h[(size_t)NN * NH];   // x@W1 (UNscaled), fp16
__device__ float  g_h2[(size_t)NN * NC];    // (r@W2)*norm_src

#define ADD2(acc, v) asm("add.rn.f32x2 %0, %0, %1;" : "+l"(acc) : "l"(v))
#define CP16(dst, src, sz) \
    asm volatile("cp.async.cg.shared.global [%0], [%1], 16, %2;" \
                 :: "r"(dst), "l"(src), "r"(sz))

__device__ __forceinline__ unsigned smem_u32(const void* p) {
    return (unsigned)__cvta_generic_to_shared(p);
}

// ---------------- in-degree histogram, 4 edges/thread ----------------
__global__ void k_hist(const int* __restrict__ dst) {
    int i = blockIdx.x * blockDim.x + threadIdx.x;
    if (i * 4 < NE) {
        int4 d = *(const int4*)&dst[i * 4];
        atomicAdd(&g_deg[NN + d.x], 1);
        atomicAdd(&g_deg[NN + d.y], 1);
        atomicAdd(&g_deg[NN + d.z], 1);
        atomicAdd(&g_deg[NN + d.w], 1);
    }
}

// ---------------- scan phase A ----------------
__global__ void __launch_bounds__(256) k_scanA() {
    __shared__ int sh[256];
    const int t = threadIdx.x;
    int i0 = blockIdx.x * 512 + 2 * t;
    int s = 0;
    if (i0 < NN) s += g_deg[NN + i0];
    if (i0 + 1 < NN) s += g_deg[NN + i0 + 1];
    sh[t] = s;
    __syncthreads();
    for (int off = 128; off > 0; off >>= 1) {
        if (t < off) sh[t] += sh[t + off];
        __syncthreads();
    }
    if (t == 0) g_part[blockIdx.x] = sh[0];
    if (t == 1 && blockIdx.x == 0) g_rowptr[NN] = NE;
}

// ---------------- scan phase C ----------------
__global__ void __launch_bounds__(256) k_scanC() {
    __shared__ int part[256];
    __shared__ int loc[256];
    const int t = threadIdx.x;
    const int b = blockIdx.x;

    part[t] = (t < 196) ? g_part[t] : 0;
    __syncthreads();
    for (int off = 1; off < 256; off <<= 1) {
        int u = (t >= off) ? part[t - off] : 0;
        __syncthreads();
        part[t] += u;
        __syncthreads();
    }
    int offset = (b > 0) ? part[b - 1] : 0;

    int i0 = b * 512 + 2 * t;
    int d0 = (i0 < NN) ? g_deg[NN + i0] : 0;
    int d1 = (i0 + 1 < NN) ? g_deg[NN + i0 + 1] : 0;
    loc[t] = d0 + d1;
    __syncthreads();
    for (int off = 1; off < 256; off <<= 1) {
        int u = (t >= off) ? loc[t - off] : 0;
        __syncthreads();
        loc[t] += u;
        __syncthreads();
    }
    int excl = offset + ((t > 0) ? loc[t - 1] : 0);
    if (i0 < NN)     { g_rowptr[i0] = excl;          g_cursor[i0] = excl; }
    if (i0 + 1 < NN) { g_rowptr[i0 + 1] = excl + d0; g_cursor[i0 + 1] = excl + d0; }
}

// ---------------- fill CSR + out-degree, 4 edges/thread ----------------
__global__ void k_fill(const int* __restrict__ src, const int* __restrict__ dst) {
    int i = blockIdx.x * blockDim.x + threadIdx.x;
    if (i * 4 < NE) {
        int4 s = *(const int4*)&src[i * 4];
        int4 d = *(const int4*)&dst[i * 4];
        int p0 = atomicAdd(&g_cursor[d.x], 1);
        int p1 = atomicAdd(&g_cursor[d.y], 1);
        int p2 = atomicAdd(&g_cursor[d.z], 1);
        int p3 = atomicAdd(&g_cursor[d.w], 1);
        g_col[p0] = s.x;
        g_col[p1] = s.y;
        g_col[p2] = s.z;
        g_col[p3] = s.w;
        atomicAdd(&g_deg[s.x], 1);
        atomicAdd(&g_deg[s.y], 1);
        atomicAdd(&g_deg[s.z], 1);
        atomicAdd(&g_deg[s.w], 1);
    }
}

// ---------------- norm_src precompute ----------------
__global__ void k_ns() {
    int i = blockIdx.x * blockDim.x + threadIdx.x;
    if (i < NN) g_ns[i] = rsqrtf((float)max(g_deg[i], 1));
}

// ---------------- layer-1 GEMM: h1h = fp16(x @ W1)  (UNscaled) ----------------
// 256 nodes x 64 feats/block, cp.async double-buffered.
// Xs row layout: idx = nl*20 + (nl>>3)*4 + f  (16B pad per 8 rows -> bank-
// conflict-free column reads, cp.async stays 16B-aligned).
#define XS_IDX(nl, f) ((nl) * 20 + (((nl) >> 3) << 2) + (f))
#define XS_BUF 5248                           // floats per X buffer (255*20+124+20 -> 5244, pad)
#define WS_OFF (2 * XS_BUF)
#define GEMM_SMEM ((2 * XS_BUF + 2 * 16 * 64) * 4)

__global__ void __launch_bounds__(256, 2) k_gemm1(const float* __restrict__ x,
                                                  const float* __restrict__ W1) {
    extern __shared__ __align__(16) float sm[];

    const int tid = threadIdx.x;
    const int tx = tid & 7;
    const int ty = tid >> 3;
    const int n0 = blockIdx.x * 256;
    const int wkk = tid >> 4, wf4 = tid & 15;

    unsigned long long accp[8][4];
    #pragma unroll
    for (int i = 0; i < 8; i++)
        #pragma unroll
        for (int j = 0; j < 4; j++) accp[i][j] = 0ull;

    auto issue = [&](int kc) {
        float* Xb = sm + (kc & 1) * XS_BUF;
        #pragma unroll
        for (int it = 0; it < 4; it++) {
            int i = tid + it * 256;
            int nl = i >> 2, f4 = i & 3;
            int n = n0 + nl;
            unsigned d = smem_u32(Xb + XS_IDX(nl, f4 * 4));
            const float* s = &x[(size_t)n * NF + kc * 16 + f4 * 4];
            CP16(d, s, (n < NN) ? 16 : 0);
        }
        float* Wb = sm + WS_OFF + (kc & 1) * (16 * 64);
        unsigned dw = smem_u32(Wb + wkk * 64 + wf4 * 4);
        const float* sw = &W1[(size_t)(kc * 16 + wkk) * NH + wf4 * 4];
        CP16(dw, sw, 16);
        asm volatile("cp.async.commit_group;");
    };

    issue(0);
    for (int kc = 0; kc < NF / 16; kc++) {
        if (kc + 1 < NF / 16) {
            issue(kc + 1);
            asm volatile("cp.async.wait_group 1;");
        } else {
            asm volatile("cp.async.wait_group 0;");
        }
        __syncthreads();
        const float* Xb = sm + (kc & 1) * XS_BUF;
        const float* Wb = sm + WS_OFF + (kc & 1) * (16 * 64);

        #pragma unroll
        for (int kk2 = 0; kk2 < 8; kk2++) {
            float2 av2[8];
            #pragma unroll
            for (int i = 0; i < 8; i++)
                av2[i] = *(const float2*)&Xb[XS_IDX(ty * 8 + i, kk2 * 2)];
            #pragma unroll
            for (int h = 0; h < 2; h++) {
                const int kk = kk2 * 2 + h;
                ulonglong2 w0 = *(const ulonglong2*)(Wb + kk * 64 + tx * 8);
                ulonglong2 w1 = *(const ulonglong2*)(Wb + kk * 64 + tx * 8 + 4);
                unsigned long long bp[4] = {w0.x, w0.y, w1.x, w1.y};
                #pragma unroll
                for (int i = 0; i < 8; i++) {
                    float a = h ? av2[i].y : av2[i].x;
                    unsigned long long ad;
                    asm("mov.b64 %0, {%1, %1};" : "=l"(ad) : "f"(a));
                    #pragma unroll
                    for (int jj = 0; jj < 4; jj++)
                        asm("fma.rn.f32x2 %0, %1, %2, %0;"
                            : "+l"(accp[i][jj]) : "l"(ad), "l"(bp[jj]));
                }
            }
        }
        __syncthreads();
    }

    #pragma unroll
    for (int i = 0; i < 8; i++) {
        int n = n0 + ty * 8 + i;
        if (n < NN) {
            __half2 h[4];
            #pragma unroll
            for (int jj = 0; jj < 4; jj++) {
                float lo, hi;
                asm("mov.b64 {%0, %1}, %2;" : "=f"(lo), "=f"(hi) : "l"(accp[i][jj]));
                h[jj] = __floats2half2_rn(lo, hi);
            }
            *(uint4*)&g_h1h[(size_t)n * NH + tx * 8] = *(uint4*)h;
        }
    }
}

// ---------------- fused: gather1 (with per-src ns) + relu + hidden GEMM ----------------
__global__ void __launch_bounds__(256) k_gather1h(const float* __restrict__ b1,
                                                  const float* __restrict__ W2) {
    __shared__ __align__(16) float Rs[32][NH];
    __shared__ __align__(16) float W2s[NH * NC];

    const int tid = threadIdx.x;
    const int nl = tid >> 3;
    const int lane = tid & 7;
    const int g = blockIdx.x * 32 + nl;

    *(float4*)&W2s[tid * 4] = *(const float4*)&W2[tid * 4];

    const int s0 = g_rowptr[g];
    const int s1 = g_rowptr[g + 1];
    float acc[8] = {};

    int j = s0;
    for (; j + 8 <= s1; j += 8) {
        int c[8];
        #pragma unroll
        for (int q = 0; q < 8; q++) c[q] = __ldg(&g_col[j + q]);
        float nsv[8];
        #pragma unroll
        for (int q = 0; q < 8; q++) nsv[q] = __ldg(&g_ns[c[q]]);
        #pragma unroll
        for (int q = 0; q < 8; q++) {
            uint4 v = *(const uint4*)&g_h1h[(size_t)c[q] * NH + lane * 8];
            const __half2* hv = (const __half2*)&v;
            #pragma unroll
            for (int p = 0; p < 4; p++) {
                float2 f = __half22float2(hv[p]);
                acc[2 * p]     = fmaf(f.x, nsv[q], acc[2 * p]);
                acc[2 * p + 1] = fmaf(f.y, nsv[q], acc[2 * p + 1]);
            }
        }
    }
    for (; j < s1; j++) {
        int c = __ldg(&g_col[j]);
        float nsv = __ldg(&g_ns[c]);
        uint4 v = *(const uint4*)&g_h1h[(size_t)c * NH + lane * 8];
        const __half2* hv = (const __half2*)&v;
        #pragma unroll
        for (int p = 0; p < 4; p++) {
            float2 f = __half22float2(hv[p]);
            acc[2 * p]     = fmaf(f.x, nsv, acc[2 * p]);
            acc[2 * p + 1] = fmaf(f.y, nsv, acc[2 * p + 1]);
        }
    }

    float nd = rsqrtf((float)max(s1 - s0, 1));
    float4 bb0 = *(const float4*)&b1[lane * 8];
    float4 bb1 = *(const float4*)&b1[lane * 8 + 4];
    float bv[8] = {bb0.x, bb0.y, bb0.z, bb0.w, bb1.x, bb1.y, bb1.z, bb1.w};
    #pragma unroll
    for (int q = 0; q < 8; q++)
        Rs[nl][lane * 8 + q] = fmaxf(fmaf(acc[q], nd, bv[q]), 0.f);
    __syncthreads();

    const int c0 = lane * 2;
    float a0 = 0.f, a1 = 0.f;
    #pragma unroll
    for (int k = 0; k < NH; k++) {
        float rv = Rs[nl][k];
        float2 w = *(const float2*)&W2s[k * NC + c0];
        a0 = fmaf(rv, w.x, a0);
        a1 = fmaf(rv, w.y, a1);
    }
    float ns = g_ns[g];
    *(float2*)&g_h2[(size_t)g * NC + c0] = make_float2(a0 * ns, a1 * ns);
}

// ---------------- layer-2 gather + log_softmax fused ----------------
__global__ void __launch_bounds__(256) k_gather2(const float* __restrict__ b2,
                                                 float* __restrict__ out) {
    int g0 = blockIdx.x * 64 + (threadIdx.x >> 2);
    const bool valid = (g0 < NN);
    const int g = valid ? g0 : (NN - 1);
    const int lane = threadIdx.x & 3;

    const int s0 = g_rowptr[g];
    const int s1 = g_rowptr[g + 1];
    unsigned long long acc0 = 0ull, acc1 = 0ull;

    int j = s0;
    for (; j + 8 <= s1; j += 8) {
        int c[8];
        #pragma unroll
        for (int q = 0; q < 8; q++) c[q] = __ldg(&g_col[j + q]);
        #pragma unroll
        for (int q = 0; q < 8; q++) {
            ulonglong2 v = *(const ulonglong2*)&g_h2[(size_t)c[q] * NC + lane * 4];
            ADD2(acc0, v.x);
            ADD2(acc1, v.y);
        }
    }
    for (; j < s1; j++) {
        int c = __ldg(&g_col[j]);
        ulonglong2 v = *(const ulonglong2*)&g_h2[(size_t)c * NC + lane * 4];
        ADD2(acc0, v.x);
        ADD2(acc1, v.y);
    }

    float nd = rsqrtf((float)max(s1 - s0, 1));
    float v[4];
    asm("mov.b64 {%0, %1}, %2;" : "=f"(v[0]), "=f"(v[1]) : "l"(acc0));
    asm("mov.b64 {%0, %1}, %2;" : "=f"(v[2]), "=f"(v[3]) : "l"(acc1));
    float4 bb = *(const float4*)&b2[lane * 4];
    v[0] = fmaf(v[0], nd, bb.x);
    v[1] = fmaf(v[1], nd, bb.y);
    v[2] = fmaf(v[2], nd, bb.z);
    v[3] = fmaf(v[3], nd, bb.w);

    float mloc = fmaxf(fmaxf(v[0], v[1]), fmaxf(v[2], v[3]));
    mloc = fmaxf(mloc, __shfl_xor_sync(0xFFFFFFFFu, mloc, 1, 4));
    mloc = fmaxf(mloc, __shfl_xor_sync(0xFFFFFFFFu, mloc, 2, 4));

    float sl = __expf(v[0] - mloc) + __expf(v[1] - mloc) +
               __expf(v[2] - mloc) + __expf(v[3] - mloc);
    sl += __shfl_xor_sync(0xFFFFFFFFu, sl, 1, 4);
    sl += __shfl_xor_sync(0xFFFFFFFFu, sl, 2, 4);
    float l = mloc + __logf(sl);

    if (valid)
        *(float4*)&out[(size_t)g * NC + lane * 4] =
            make_float4(v[0] - l, v[1] - l, v[2] - l, v[3] - l);
}

// ---------------- launch: fork CSR build onto a side stream ----------------
extern "C" void kernel_launch(void* const* d_in, const int* in_sizes, int n_in,
                              void* d_out, int out_size) {
    const float* x   = (const float*)d_in[0];
    const int*   src = (const int*)d_in[1];
    const int*   dst = (const int*)d_in[2];
    const float* W1  = (const float*)d_in[3];
    const float* b1  = (const float*)d_in[4];
    const float* W2  = (const float*)d_in[5];
    const float* b2  = (const float*)d_in[6];
    float* out = (float*)d_out;

    cudaFuncSetAttribute(k_gemm1, cudaFuncAttributeMaxDynamicSharedMemorySize,
                         GEMM_SMEM);

    // host-side objects only; intentionally not destroyed.
    cudaStream_t s1;
    cudaStreamCreateWithFlags(&s1, cudaStreamNonBlocking);
    cudaEvent_t evF, evJ;
    cudaEventCreateWithFlags(&evF, cudaEventDisableTiming);
    cudaEventCreateWithFlags(&evJ, cudaEventDisableTiming);

    void* pdeg;
    cudaGetSymbolAddress(&pdeg, g_deg);

    // fork: CSR chain on s1
    cudaEventRecord(evF, 0);
    cudaStreamWaitEvent(s1, evF, 0);
    cudaMemsetAsync(pdeg, 0, (size_t)2 * NN * sizeof(int), s1);
    k_hist<<<(NE / 4 + 255) / 256, 256, 0, s1>>>(dst);
    k_scanA<<<196, 256, 0, s1>>>();
    k_scanC<<<196, 256, 0, s1>>>();
    k_fill<<<(NE / 4 + 255) / 256, 256, 0, s1>>>(src, dst);
    k_ns<<<(NN + 255) / 256, 256, 0, s1>>>();
    cudaEventRecord(evJ, s1);

    // concurrent: dense GEMM on the main (captured) stream
    k_gemm1<<<(NN + 255) / 256, 256, GEMM_SMEM>>>(x, W1);

    // join, then gather chain
    cudaStreamWaitEvent(0, evJ, 0);
    k_gather1h<<<NN / 32, 256>>>(b1, W2);
    k_gather2<<<(NN + 63) / 64, 256>>>(b2, out);
}

// round 14
// speedup vs baseline: 1.2292x; 1.0142x over previous
#include <cuda_runtime.h>
#include <cuda_fp16.h>

#define NN 100000
#define NE 1600000
#define NF 128
#define NH 64
#define NC 16

// ---------------- scratch (static device globals) ----------------
__device__ int    g_deg[2 * NN];            // [0,NN): out-degree, [NN,2NN): in-degree
__device__ int    g_part[256];              // scan partials (196 used)
__device__ int    g_rowptr[NN + 1];
__device__ int    g_epos[NE];               // within-bucket position per edge
__device__ int    g_col[NE];                // src node per CSR slot
__device__ float  g_ns[NN];                 // rsqrt(max(outdeg,1))
__device__ __half g_h1h[(size_t)NN * NH];   // x@W1 (UNscaled), fp16
__device__ float  g_h2[(size_t)NN * NC];    // (r@W2)*norm_src

#define ADD2(acc, v) asm("add.rn.f32x2 %0, %0, %1;" : "+l"(acc) : "l"(v))
#define CP16(dst, src, sz) \
    asm volatile("cp.async.cg.shared.global [%0], [%1], 16, %2;" \
                 :: "r"(dst), "l"(src), "r"(sz))

__device__ __forceinline__ unsigned smem_u32(const void* p) {
    return (unsigned)__cvta_generic_to_shared(p);
}

// ---------------- histogram + position record, 4 edges/thread ----------------
__global__ void k_hist(const int* __restrict__ src, const int* __restrict__ dst) {
    int i = blockIdx.x * blockDim.x + threadIdx.x;
    if (i * 4 < NE) {
        int4 s = *(const int4*)&src[i * 4];
        int4 d = *(const int4*)&dst[i * 4];
        int4 p;
        p.x = atomicAdd(&g_deg[NN + d.x], 1);
        p.y = atomicAdd(&g_deg[NN + d.y], 1);
        p.z = atomicAdd(&g_deg[NN + d.z], 1);
        p.w = atomicAdd(&g_deg[NN + d.w], 1);
        *(int4*)&g_epos[i * 4] = p;
        atomicAdd(&g_deg[s.x], 1);
        atomicAdd(&g_deg[s.y], 1);
        atomicAdd(&g_deg[s.z], 1);
        atomicAdd(&g_deg[s.w], 1);
    }
}

// ---------------- norm_src precompute (needs only odeg) ----------------
__global__ void k_ns() {
    int i = blockIdx.x * blockDim.x + threadIdx.x;
    if (i < NN) g_ns[i] = rsqrtf((float)max(g_deg[i], 1));
}

// ---------------- scan phase A ----------------
__global__ void __launch_bounds__(256) k_scanA() {
    __shared__ int sh[256];
    const int t = threadIdx.x;
    int i0 = blockIdx.x * 512 + 2 * t;
    int s = 0;
    if (i0 < NN) s += g_deg[NN + i0];
    if (i0 + 1 < NN) s += g_deg[NN + i0 + 1];
    sh[t] = s;
    __syncthreads();
    for (int off = 128; off > 0; off >>= 1) {
        if (t < off) sh[t] += sh[t + off];
        __syncthreads();
    }
    if (t == 0) g_part[blockIdx.x] = sh[0];
    if (t == 1 && blockIdx.x == 0) g_rowptr[NN] = NE;
}

// ---------------- scan phase C ----------------
__global__ void __launch_bounds__(256) k_scanC() {
    __shared__ int part[256];
    __shared__ int loc[256];
    const int t = threadIdx.x;
    const int b = blockIdx.x;

    part[t] = (t < 196) ? g_part[t] : 0;
    __syncthreads();
    for (int off = 1; off < 256; off <<= 1) {
        int u = (t >= off) ? part[t - off] : 0;
        __syncthreads();
        part[t] += u;
        __syncthreads();
    }
    int offset = (b > 0) ? part[b - 1] : 0;

    int i0 = b * 512 + 2 * t;
    int d0 = (i0 < NN) ? g_deg[NN + i0] : 0;
    int d1 = (i0 + 1 < NN) ? g_deg[NN + i0 + 1] : 0;
    loc[t] = d0 + d1;
    __syncthreads();
    for (int off = 1; off < 256; off <<= 1) {
        int u = (t >= off) ? loc[t - off] : 0;
        __syncthreads();
        loc[t] += u;
        __syncthreads();
    }
    int excl = offset + ((t > 0) ? loc[t - 1] : 0);
    if (i0 < NN)     g_rowptr[i0] = excl;
    if (i0 + 1 < NN) g_rowptr[i0 + 1] = excl + d0;
}

// ---------------- fill CSR: atomic-free, 4 edges/thread ----------------
__global__ void k_fill(const int* __restrict__ src, const int* __restrict__ dst) {
    int i = blockIdx.x * blockDim.x + threadIdx.x;
    if (i * 4 < NE) {
        int4 s = *(const int4*)&src[i * 4];
        int4 d = *(const int4*)&dst[i * 4];
        int4 p = *(const int4*)&g_epos[i * 4];
        g_col[g_rowptr[d.x] + p.x] = s.x;
        g_col[g_rowptr[d.y] + p.y] = s.y;
        g_col[g_rowptr[d.z] + p.z] = s.z;
        g_col[g_rowptr[d.w] + p.w] = s.w;
    }
}

// ---------------- layer-1 GEMM: h1h = fp16(x @ W1)  (UNscaled) ----------------
// 256 nodes x 64 feats/block, cp.async double-buffered.
// Xs row layout: idx = nl*20 + (nl>>3)*4 + f  (16B pad per 8 rows -> bank-
// conflict-free column reads, cp.async stays 16B-aligned).
#define XS_IDX(nl, f) ((nl) * 20 + (((nl) >> 3) << 2) + (f))
#define XS_BUF 5248
#define WS_OFF (2 * XS_BUF)
#define GEMM_SMEM ((2 * XS_BUF + 2 * 16 * 64) * 4)

__global__ void __launch_bounds__(256, 2) k_gemm1(const float* __restrict__ x,
                                                  const float* __restrict__ W1) {
    extern __shared__ __align__(16) float sm[];

    const int tid = threadIdx.x;
    const int tx = tid & 7;
    const int ty = tid >> 3;
    const int n0 = blockIdx.x * 256;
    const int wkk = tid >> 4, wf4 = tid & 15;

    unsigned long long accp[8][4];
    #pragma unroll
    for (int i = 0; i < 8; i++)
        #pragma unroll
        for (int j = 0; j < 4; j++) accp[i][j] = 0ull;

    auto issue = [&](int kc) {
        float* Xb = sm + (kc & 1) * XS_BUF;
        #pragma unroll
        for (int it = 0; it < 4; it++) {
            int i = tid + it * 256;
            int nl = i >> 2, f4 = i & 3;
            int n = n0 + nl;
            unsigned d = smem_u32(Xb + XS_IDX(nl, f4 * 4));
            const float* s = &x[(size_t)n * NF + kc * 16 + f4 * 4];
            CP16(d, s, (n < NN) ? 16 : 0);
        }
        float* Wb = sm + WS_OFF + (kc & 1) * (16 * 64);
        unsigned dw = smem_u32(Wb + wkk * 64 + wf4 * 4);
        const float* sw = &W1[(size_t)(kc * 16 + wkk) * NH + wf4 * 4];
        CP16(dw, sw, 16);
        asm volatile("cp.async.commit_group;");
    };

    issue(0);
    for (int kc = 0; kc < NF / 16; kc++) {
        if (kc + 1 < NF / 16) {
            issue(kc + 1);
            asm volatile("cp.async.wait_group 1;");
        } else {
            asm volatile("cp.async.wait_group 0;");
        }
        __syncthreads();
        const float* Xb = sm + (kc & 1) * XS_BUF;
        const float* Wb = sm + WS_OFF + (kc & 1) * (16 * 64);

        #pragma unroll
        for (int kk2 = 0; kk2 < 8; kk2++) {
            float2 av2[8];
            #pragma unroll
            for (int i = 0; i < 8; i++)
                av2[i] = *(const float2*)&Xb[XS_IDX(ty * 8 + i, kk2 * 2)];
            #pragma unroll
            for (int h = 0; h < 2; h++) {
                const int kk = kk2 * 2 + h;
                ulonglong2 w0 = *(const ulonglong2*)(Wb + kk * 64 + tx * 8);
                ulonglong2 w1 = *(const ulonglong2*)(Wb + kk * 64 + tx * 8 + 4);
                unsigned long long bp[4] = {w0.x, w0.y, w1.x, w1.y};
                #pragma unroll
                for (int i = 0; i < 8; i++) {
                    float a = h ? av2[i].y : av2[i].x;
                    unsigned long long ad;
                    asm("mov.b64 %0, {%1, %1};" : "=l"(ad) : "f"(a));
                    #pragma unroll
                    for (int jj = 0; jj < 4; jj++)
                        asm("fma.rn.f32x2 %0, %1, %2, %0;"
                            : "+l"(accp[i][jj]) : "l"(ad), "l"(bp[jj]));
                }
            }
        }
        __syncthreads();
    }

    #pragma unroll
    for (int i = 0; i < 8; i++) {
        int n = n0 + ty * 8 + i;
        if (n < NN) {
            __half2 h[4];
            #pragma unroll
            for (int jj = 0; jj < 4; jj++) {
                float lo, hi;
                asm("mov.b64 {%0, %1}, %2;" : "=f"(lo), "=f"(hi) : "l"(accp[i][jj]));
                h[jj] = __floats2half2_rn(lo, hi);
            }
            *(uint4*)&g_h1h[(size_t)n * NH + tx * 8] = *(uint4*)h;
        }
    }
}

// ---------------- fused: gather1 (with per-src ns) + relu + hidden GEMM ----------------
__global__ void __launch_bounds__(256) k_gather1h(const float* __restrict__ b1,
                                                  const float* __restrict__ W2) {
    __shared__ __align__(16) float Rs[32][NH];
    __shared__ __align__(16) float W2s[NH * NC];

    const int tid = threadIdx.x;
    const int nl = tid >> 3;
    const int lane = tid & 7;
    const int g = blockIdx.x * 32 + nl;

    *(float4*)&W2s[tid * 4] = *(const float4*)&W2[tid * 4];

    const int s0 = g_rowptr[g];
    const int s1 = g_rowptr[g + 1];
    float acc[8] = {};

    int j = s0;
    for (; j + 8 <= s1; j += 8) {
        int c[8];
        #pragma unroll
        for (int q = 0; q < 8; q++) c[q] = __ldg(&g_col[j + q]);
        float nsv[8];
        #pragma unroll
        for (int q = 0; q < 8; q++) nsv[q] = __ldg(&g_ns[c[q]]);
        #pragma unroll
        for (int q = 0; q < 8; q++) {
            uint4 v = *(const uint4*)&g_h1h[(size_t)c[q] * NH + lane * 8];
            const __half2* hv = (const __half2*)&v;
            #pragma unroll
            for (int p = 0; p < 4; p++) {
                float2 f = __half22float2(hv[p]);
                acc[2 * p]     = fmaf(f.x, nsv[q], acc[2 * p]);
                acc[2 * p + 1] = fmaf(f.y, nsv[q], acc[2 * p + 1]);
            }
        }
    }
    for (; j < s1; j++) {
        int c = __ldg(&g_col[j]);
        float nsv = __ldg(&g_ns[c]);
        uint4 v = *(const uint4*)&g_h1h[(size_t)c * NH + lane * 8];
        const __half2* hv = (const __half2*)&v;
        #pragma unroll
        for (int p = 0; p < 4; p++) {
            float2 f = __half22float2(hv[p]);
            acc[2 * p]     = fmaf(f.x, nsv, acc[2 * p]);
            acc[2 * p + 1] = fmaf(f.y, nsv, acc[2 * p + 1]);
        }
    }

    float nd = rsqrtf((float)max(s1 - s0, 1));
    float4 bb0 = *(const float4*)&b1[lane * 8];
    float4 bb1 = *(const float4*)&b1[lane * 8 + 4];
    float bv[8] = {bb0.x, bb0.y, bb0.z, bb0.w, bb1.x, bb1.y, bb1.z, bb1.w};
    #pragma unroll
    for (int q = 0; q < 8; q++)
        Rs[nl][lane * 8 + q] = fmaxf(fmaf(acc[q], nd, bv[q]), 0.f);
    __syncthreads();

    const int c0 = lane * 2;
    float a0 = 0.f, a1 = 0.f;
    #pragma unroll
    for (int k = 0; k < NH; k++) {
        float rv = Rs[nl][k];
        float2 w = *(const float2*)&W2s[k * NC + c0];
        a0 = fmaf(rv, w.x, a0);
        a1 = fmaf(rv, w.y, a1);
    }
    float ns = g_ns[g];
    *(float2*)&g_h2[(size_t)g * NC + c0] = make_float2(a0 * ns, a1 * ns);
}

// ---------------- layer-2 gather + log_softmax fused ----------------
__global__ void __launch_bounds__(256) k_gather2(const float* __restrict__ b2,
                                                 float* __restrict__ out) {
    int g0 = blockIdx.x * 64 + (threadIdx.x >> 2);
    const bool valid = (g0 < NN);
    const int g = valid ? g0 : (NN - 1);
    const int lane = threadIdx.x & 3;

    const int s0 = g_rowptr[g];
    const int s1 = g_rowptr[g + 1];
    unsigned long long acc0 = 0ull, acc1 = 0ull;

    int j = s0;
    for (; j + 8 <= s1; j += 8) {
        int c[8];
        #pragma unroll
        for (int q = 0; q < 8; q++) c[q] = __ldg(&g_col[j + q]);
        #pragma unroll
        for (int q = 0; q < 8; q++) {
            ulonglong2 v = *(const ulonglong2*)&g_h2[(size_t)c[q] * NC + lane * 4];
            ADD2(acc0, v.x);
            ADD2(acc1, v.y);
        }
    }
    for (; j < s1; j++) {
        int c = __ldg(&g_col[j]);
        ulonglong2 v = *(const ulonglong2*)&g_h2[(size_t)c * NC + lane * 4];
        ADD2(acc0, v.x);
        ADD2(acc1, v.y);
    }

    float nd = rsqrtf((float)max(s1 - s0, 1));
    float v[4];
    asm("mov.b64 {%0, %1}, %2;" : "=f"(v[0]), "=f"(v[1]) : "l"(acc0));
    asm("mov.b64 {%0, %1}, %2;" : "=f"(v[2]), "=f"(v[3]) : "l"(acc1));
    float4 bb = *(const float4*)&b2[lane * 4];
    v[0] = fmaf(v[0], nd, bb.x);
    v[1] = fmaf(v[1], nd, bb.y);
    v[2] = fmaf(v[2], nd, bb.z);
    v[3] = fmaf(v[3], nd, bb.w);

    float mloc = fmaxf(fmaxf(v[0], v[1]), fmaxf(v[2], v[3]));
    mloc = fmaxf(mloc, __shfl_xor_sync(0xFFFFFFFFu, mloc, 1, 4));
    mloc = fmaxf(mloc, __shfl_xor_sync(0xFFFFFFFFu, mloc, 2, 4));

    float sl = __expf(v[0] - mloc) + __expf(v[1] - mloc) +
               __expf(v[2] - mloc) + __expf(v[3] - mloc);
    sl += __shfl_xor_sync(0xFFFFFFFFu, sl, 1, 4);
    sl += __shfl_xor_sync(0xFFFFFFFFu, sl, 2, 4);
    float l = mloc + __logf(sl);

    if (valid)
        *(float4*)&out[(size_t)g * NC + lane * 4] =
            make_float4(v[0] - l, v[1] - l, v[2] - l, v[3] - l);
}

// ---------------- launch: fork CSR build onto a side stream ----------------
extern "C" void kernel_launch(void* const* d_in, const int* in_sizes, int n_in,
                              void* d_out, int out_size) {
    const float* x   = (const float*)d_in[0];
    const int*   src = (const int*)d_in[1];
    const int*   dst = (const int*)d_in[2];
    const float* W1  = (const float*)d_in[3];
    const float* b1  = (const float*)d_in[4];
    const float* W2  = (const float*)d_in[5];
    const float* b2  = (const float*)d_in[6];
    float* out = (float*)d_out;

    cudaFuncSetAttribute(k_gemm1, cudaFuncAttributeMaxDynamicSharedMemorySize,
                         GEMM_SMEM);

    // host-side objects only; intentionally not destroyed.
    cudaStream_t s1;
    cudaStreamCreateWithFlags(&s1, cudaStreamNonBlocking);
    cudaEvent_t evF, evJ;
    cudaEventCreateWithFlags(&evF, cudaEventDisableTiming);
    cudaEventCreateWithFlags(&evJ, cudaEventDisableTiming);

    void* pdeg;
    cudaGetSymbolAddress(&pdeg, g_deg);

    // fork: CSR chain on s1
    cudaEventRecord(evF, 0);
    cudaStreamWaitEvent(s1, evF, 0);
    cudaMemsetAsync(pdeg, 0, (size_t)2 * NN * sizeof(int), s1);
    k_hist<<<(NE / 4 + 255) / 256, 256, 0, s1>>>(src, dst);
    k_ns<<<(NN + 255) / 256, 256, 0, s1>>>();
    k_scanA<<<196, 256, 0, s1>>>();
    k_scanC<<<196, 256, 0, s1>>>();
    k_fill<<<(NE / 4 + 255) / 256, 256, 0, s1>>>(src, dst);
    cudaEventRecord(evJ, s1);

    // concurrent: dense GEMM on the main (captured) stream
    k_gemm1<<<(NN + 255) / 256, 256, GEMM_SMEM>>>(x, W1);

    // join, then gather chain
    cudaStreamWaitEvent(0, evJ, 0);
    k_gather1h<<<NN / 32, 256>>>(b1, W2);
    k_gather2<<<(NN + 63) / 64, 256>>>(b2, out);
}

// round 15
// speedup vs baseline: 1.3812x; 1.1237x over previous
#include <cuda_runtime.h>
#include <cuda_fp16.h>

#define NN 100000
#define NE 1600000
#define NF 128
#define NH 64
#define NC 16

// ---------------- scratch (static device globals) ----------------
__device__ int    g_deg[2 * NN];            // [0,NN): out-degree, [NN,2NN): in-degree
__device__ int    g_part[256];              // scan partials (196 used)
__device__ int    g_rowptr[NN + 1];
__device__ int    g_epos[NE];               // within-bucket position per edge
__device__ int    g_col[NE];                // src node per CSR slot
__device__ float  g_ns[NN];                 // rsqrt(max(outdeg,1))
__device__ __half g_h1h[(size_t)NN * NH];   // x@W1 (UNscaled), fp16
__device__ float  g_h2[(size_t)NN * NC];    // (r@W2)*norm_src

#define ADD2(acc, v) asm("add.rn.f32x2 %0, %0, %1;" : "+l"(acc) : "l"(v))

// ---------------- histogram + position record, 4 edges/thread ----------------
__global__ void k_hist(const int* __restrict__ src, const int* __restrict__ dst) {
    int i = blockIdx.x * blockDim.x + threadIdx.x;
    if (i * 4 < NE) {
        int4 s = *(const int4*)&src[i * 4];
        int4 d = *(const int4*)&dst[i * 4];
        int4 p;
        p.x = atomicAdd(&g_deg[NN + d.x], 1);
        p.y = atomicAdd(&g_deg[NN + d.y], 1);
        p.z = atomicAdd(&g_deg[NN + d.z], 1);
        p.w = atomicAdd(&g_deg[NN + d.w], 1);
        *(int4*)&g_epos[i * 4] = p;
        atomicAdd(&g_deg[s.x], 1);
        atomicAdd(&g_deg[s.y], 1);
        atomicAdd(&g_deg[s.z], 1);
        atomicAdd(&g_deg[s.w], 1);
    }
}

// ---------------- norm_src precompute (needs only odeg) ----------------
__global__ void k_ns() {
    int i = blockIdx.x * blockDim.x + threadIdx.x;
    if (i < NN) g_ns[i] = rsqrtf((float)max(g_deg[i], 1));
}

// ---------------- scan phase A ----------------
__global__ void __launch_bounds__(256) k_scanA() {
    __shared__ int sh[256];
    const int t = threadIdx.x;
    int i0 = blockIdx.x * 512 + 2 * t;
    int s = 0;
    if (i0 < NN) s += g_deg[NN + i0];
    if (i0 + 1 < NN) s += g_deg[NN + i0 + 1];
    sh[t] = s;
    __syncthreads();
    for (int off = 128; off > 0; off >>= 1) {
        if (t < off) sh[t] += sh[t + off];
        __syncthreads();
    }
    if (t == 0) g_part[blockIdx.x] = sh[0];
    if (t == 1 && blockIdx.x == 0) g_rowptr[NN] = NE;
}

// ---------------- scan phase C ----------------
__global__ void __launch_bounds__(256) k_scanC() {
    __shared__ int part[256];
    __shared__ int loc[256];
    const int t = threadIdx.x;
    const int b = blockIdx.x;

    part[t] = (t < 196) ? g_part[t] : 0;
    __syncthreads();
    for (int off = 1; off < 256; off <<= 1) {
        int u = (t >= off) ? part[t - off] : 0;
        __syncthreads();
        part[t] += u;
        __syncthreads();
    }
    int offset = (b > 0) ? part[b - 1] : 0;

    int i0 = b * 512 + 2 * t;
    int d0 = (i0 < NN) ? g_deg[NN + i0] : 0;
    int d1 = (i0 + 1 < NN) ? g_deg[NN + i0 + 1] : 0;
    loc[t] = d0 + d1;
    __syncthreads();
    for (int off = 1; off < 256; off <<= 1) {
        int u = (t >= off) ? loc[t - off] : 0;
        __syncthreads();
        loc[t] += u;
        __syncthreads();
    }
    int excl = offset + ((t > 0) ? loc[t - 1] : 0);
    if (i0 < NN)     g_rowptr[i0] = excl;
    if (i0 + 1 < NN) g_rowptr[i0 + 1] = excl + d0;
}

// ---------------- fill CSR: atomic-free, 4 edges/thread ----------------
__global__ void k_fill(const int* __restrict__ src, const int* __restrict__ dst) {
    int i = blockIdx.x * blockDim.x + threadIdx.x;
    if (i * 4 < NE) {
        int4 s = *(const int4*)&src[i * 4];
        int4 d = *(const int4*)&dst[i * 4];
        int4 p = *(const int4*)&g_epos[i * 4];
        g_col[g_rowptr[d.x] + p.x] = s.x;
        g_col[g_rowptr[d.y] + p.y] = s.y;
        g_col[g_rowptr[d.z] + p.z] = s.z;
        g_col[g_rowptr[d.w] + p.w] = s.w;
    }
}

// ---------------- layer-1 GEMM via HMMA: h1h = fp16(x @ W1) (UNscaled) ----------------
// 128 nodes/CTA, 256 threads = 8 warps (16 nodes/warp), mma.m16n8k16 fp16->fp32.
// smem: xh[128][136] fp16 (272B row stride, conflict-free) + per-lane W fragments.
#define XH_STRIDE 136                       // halves per row
#define XH_BYTES (128 * XH_STRIDE * 2)      // 34816
#define WF_OFF XH_BYTES
#define GEMM_SMEM (XH_BYTES + 8 * 8 * 32 * 8)   // + 16KB wf = 51200

__global__ void __launch_bounds__(256) k_gemm1(const float* __restrict__ x,
                                               const float* __restrict__ W1) {
    extern __shared__ __align__(16) char sm[];
    __half* xh = (__half*)sm;
    uint2* wf = (uint2*)(sm + WF_OFF);      // [ks][nb][lane]

    const int tid = threadIdx.x;
    const int warp = tid >> 5;
    const int lane = tid & 31;
    const int n0 = blockIdx.x * 128;

    // ---- build W fragments: 2048 uint2, 8 per thread ----
    #pragma unroll
    for (int it = 0; it < 8; it++) {
        int e = tid + it * 256;             // [0,2048)
        int ks = e >> 8;
        int nb = (e >> 5) & 7;
        int ln = e & 31;
        int g = ln >> 2, tc = ln & 3;
        int k0 = ks * 16 + tc * 2;
        int n = nb * 8 + g;
        __half2 b0 = __floats2half2_rn(W1[(size_t)k0 * NH + n],
                                       W1[(size_t)(k0 + 1) * NH + n]);
        __half2 b1 = __floats2half2_rn(W1[(size_t)(k0 + 8) * NH + n],
                                       W1[(size_t)(k0 + 9) * NH + n]);
        uint2 w;
        w.x = *(unsigned*)&b0;
        w.y = *(unsigned*)&b1;
        wf[e] = w;
    }

    // ---- load x (fp32, coalesced LDG.128) -> convert -> fp16 smem ----
    #pragma unroll
    for (int it = 0; it < 16; it++) {
        int idx = tid + it * 256;           // float4 index, [0,4096)
        int node = idx >> 5;                // 32 float4 per node
        int k4 = idx & 31;
        int n = n0 + node;
        float4 v = make_float4(0.f, 0.f, 0.f, 0.f);
        if (n < NN) v = *(const float4*)&x[(size_t)n * NF + k4 * 4];
        __half2 h0 = __floats2half2_rn(v.x, v.y);
        __half2 h1 = __floats2half2_rn(v.z, v.w);
        uint2 pkt;
        pkt.x = *(unsigned*)&h0;
        pkt.y = *(unsigned*)&h1;
        *(uint2*)&xh[node * XH_STRIDE + k4 * 4] = pkt;
    }
    __syncthreads();

    // ---- mma mainloop: warp owns nodes [warp*16, warp*16+16) ----
    const int base = warp * 16;
    const int g = lane >> 2, tc = lane & 3;
    float acc[8][4];
    #pragma unroll
    for (int nb = 0; nb < 8; nb++)
        #pragma unroll
        for (int q = 0; q < 4; q++) acc[nb][q] = 0.f;

    #pragma unroll
    for (int ks = 0; ks < 8; ks++) {
        int k0 = ks * 16 + tc * 2;
        unsigned a0 = *(const unsigned*)&xh[(base + g) * XH_STRIDE + k0];
        unsigned a1 = *(const unsigned*)&xh[(base + g + 8) * XH_STRIDE + k0];
        unsigned a2 = *(const unsigned*)&xh[(base + g) * XH_STRIDE + k0 + 8];
        unsigned a3 = *(const unsigned*)&xh[(base + g + 8) * XH_STRIDE + k0 + 8];
        #pragma unroll
        for (int nb = 0; nb < 8; nb++) {
            uint2 b = wf[(ks * 8 + nb) * 32 + lane];
            asm volatile(
                "mma.sync.aligned.m16n8k16.row.col.f32.f16.f16.f32 "
                "{%0,%1,%2,%3}, {%4,%5,%6,%7}, {%8,%9}, {%0,%1,%2,%3};"
                : "+f"(acc[nb][0]), "+f"(acc[nb][1]),
                  "+f"(acc[nb][2]), "+f"(acc[nb][3])
                : "r"(a0), "r"(a1), "r"(a2), "r"(a3), "r"(b.x), "r"(b.y));
        }
    }

    // ---- epilogue: D[g][tc*2..+1], D[g+8][tc*2..+1] per nb -> fp16 ----
    const int n_lo = n0 + base + g;
    const int n_hi = n_lo + 8;
    #pragma unroll
    for (int nb = 0; nb < 8; nb++) {
        int c = nb * 8 + tc * 2;
        if (n_lo < NN) {
            __half2 h = __floats2half2_rn(acc[nb][0], acc[nb][1]);
            *(__half2*)&g_h1h[(size_t)n_lo * NH + c] = h;
        }
        if (n_hi < NN) {
            __half2 h = __floats2half2_rn(acc[nb][2], acc[nb][3]);
            *(__half2*)&g_h1h[(size_t)n_hi * NH + c] = h;
        }
    }
}

// ---------------- fused: gather1 (with per-src ns) + relu + hidden GEMM ----------------
__global__ void __launch_bounds__(256) k_gather1h(const float* __restrict__ b1,
                                                  const float* __restrict__ W2) {
    __shared__ __align__(16) float Rs[32][NH];
    __shared__ __align__(16) float W2s[NH * NC];

    const int tid = threadIdx.x;
    const int nl = tid >> 3;
    const int lane = tid & 7;
    const int g = blockIdx.x * 32 + nl;

    *(float4*)&W2s[tid * 4] = *(const float4*)&W2[tid * 4];

    const int s0 = g_rowptr[g];
    const int s1 = g_rowptr[g + 1];
    float acc[8] = {};

    int j = s0;
    for (; j + 8 <= s1; j += 8) {
        int c[8];
        #pragma unroll
        for (int q = 0; q < 8; q++) c[q] = __ldg(&g_col[j + q]);
        float nsv[8];
        #pragma unroll
        for (int q = 0; q < 8; q++) nsv[q] = __ldg(&g_ns[c[q]]);
        #pragma unroll
        for (int q = 0; q < 8; q++) {
            uint4 v = *(const uint4*)&g_h1h[(size_t)c[q] * NH + lane * 8];
            const __half2* hv = (const __half2*)&v;
            #pragma unroll
            for (int p = 0; p < 4; p++) {
                float2 f = __half22float2(hv[p]);
                acc[2 * p]     = fmaf(f.x, nsv[q], acc[2 * p]);
                acc[2 * p + 1] = fmaf(f.y, nsv[q], acc[2 * p + 1]);
            }
        }
    }
    for (; j < s1; j++) {
        int c = __ldg(&g_col[j]);
        float nsv = __ldg(&g_ns[c]);
        uint4 v = *(const uint4*)&g_h1h[(size_t)c * NH + lane * 8];
        const __half2* hv = (const __half2*)&v;
        #pragma unroll
        for (int p = 0; p < 4; p++) {
            float2 f = __half22float2(hv[p]);
            acc[2 * p]     = fmaf(f.x, nsv, acc[2 * p]);
            acc[2 * p + 1] = fmaf(f.y, nsv, acc[2 * p + 1]);
        }
    }

    float nd = rsqrtf((float)max(s1 - s0, 1));
    float4 bb0 = *(const float4*)&b1[lane * 8];
    float4 bb1 = *(const float4*)&b1[lane * 8 + 4];
    float bv[8] = {bb0.x, bb0.y, bb0.z, bb0.w, bb1.x, bb1.y, bb1.z, bb1.w};
    #pragma unroll
    for (int q = 0; q < 8; q++)
        Rs[nl][lane * 8 + q] = fmaxf(fmaf(acc[q], nd, bv[q]), 0.f);
    __syncthreads();

    const int c0 = lane * 2;
    float a0 = 0.f, a1 = 0.f;
    #pragma unroll
    for (int k = 0; k < NH; k++) {
        float rv = Rs[nl][k];
        float2 w = *(const float2*)&W2s[k * NC + c0];
        a0 = fmaf(rv, w.x, a0);
        a1 = fmaf(rv, w.y, a1);
    }
    float ns = g_ns[g];
    *(float2*)&g_h2[(size_t)g * NC + c0] = make_float2(a0 * ns, a1 * ns);
}

// ---------------- layer-2 gather + log_softmax fused ----------------
__global__ void __launch_bounds__(256) k_gather2(const float* __restrict__ b2,
                                                 float* __restrict__ out) {
    int g0 = blockIdx.x * 64 + (threadIdx.x >> 2);
    const bool valid = (g0 < NN);
    const int g = valid ? g0 : (NN - 1);
    const int lane = threadIdx.x & 3;

    const int s0 = g_rowptr[g];
    const int s1 = g_rowptr[g + 1];
    unsigned long long acc0 = 0ull, acc1 = 0ull;

    int j = s0;
    for (; j + 8 <= s1; j += 8) {
        int c[8];
        #pragma unroll
        for (int q = 0; q < 8; q++) c[q] = __ldg(&g_col[j + q]);
        #pragma unroll
        for (int q = 0; q < 8; q++) {
            ulonglong2 v = *(const ulonglong2*)&g_h2[(size_t)c[q] * NC + lane * 4];
            ADD2(acc0, v.x);
            ADD2(acc1, v.y);
        }
    }
    for (; j < s1; j++) {
        int c = __ldg(&g_col[j]);
        ulonglong2 v = *(const ulonglong2*)&g_h2[(size_t)c * NC + lane * 4];
        ADD2(acc0, v.x);
        ADD2(acc1, v.y);
    }

    float nd = rsqrtf((float)max(s1 - s0, 1));
    float v[4];
    asm("mov.b64 {%0, %1}, %2;" : "=f"(v[0]), "=f"(v[1]) : "l"(acc0));
    asm("mov.b64 {%0, %1}, %2;" : "=f"(v[2]), "=f"(v[3]) : "l"(acc1));
    float4 bb = *(const float4*)&b2[lane * 4];
    v[0] = fmaf(v[0], nd, bb.x);
    v[1] = fmaf(v[1], nd, bb.y);
    v[2] = fmaf(v[2], nd, bb.z);
    v[3] = fmaf(v[3], nd, bb.w);

    float mloc = fmaxf(fmaxf(v[0], v[1]), fmaxf(v[2], v[3]));
    mloc = fmaxf(mloc, __shfl_xor_sync(0xFFFFFFFFu, mloc, 1, 4));
    mloc = fmaxf(mloc, __shfl_xor_sync(0xFFFFFFFFu, mloc, 2, 4));

    float sl = __expf(v[0] - mloc) + __expf(v[1] - mloc) +
               __expf(v[2] - mloc) + __expf(v[3] - mloc);
    sl += __shfl_xor_sync(0xFFFFFFFFu, sl, 1, 4);
    sl += __shfl_xor_sync(0xFFFFFFFFu, sl, 2, 4);
    float l = mloc + __logf(sl);

    if (valid)
        *(float4*)&out[(size_t)g * NC + lane * 4] =
            make_float4(v[0] - l, v[1] - l, v[2] - l, v[3] - l);
}

// ---------------- launch: fork CSR build onto a side stream ----------------
extern "C" void kernel_launch(void* const* d_in, const int* in_sizes, int n_in,
                              void* d_out, int out_size) {
    const float* x   = (const float*)d_in[0];
    const int*   src = (const int*)d_in[1];
    const int*   dst = (const int*)d_in[2];
    const float* W1  = (const float*)d_in[3];
    const float* b1  = (const float*)d_in[4];
    const float* W2  = (const float*)d_in[5];
    const float* b2  = (const float*)d_in[6];
    float* out = (float*)d_out;

    cudaFuncSetAttribute(k_gemm1, cudaFuncAttributeMaxDynamicSharedMemorySize,
                         GEMM_SMEM);

    // host-side objects only; intentionally not destroyed.
    cudaStream_t s1;
    cudaStreamCreateWithFlags(&s1, cudaStreamNonBlocking);
    cudaEvent_t evF, evJ;
    cudaEventCreateWithFlags(&evF, cudaEventDisableTiming);
    cudaEventCreateWithFlags(&evJ, cudaEventDisableTiming);

    void* pdeg;
    cudaGetSymbolAddress(&pdeg, g_deg);

    // fork: CSR chain on s1
    cudaEventRecord(evF, 0);
    cudaStreamWaitEvent(s1, evF, 0);
    cudaMemsetAsync(pdeg, 0, (size_t)2 * NN * sizeof(int), s1);
    k_hist<<<(NE / 4 + 255) / 256, 256, 0, s1>>>(src, dst);
    k_ns<<<(NN + 255) / 256, 256, 0, s1>>>();
    k_scanA<<<196, 256, 0, s1>>>();
    k_scanC<<<196, 256, 0, s1>>>();
    k_fill<<<(NE / 4 + 255) / 256, 256, 0, s1>>>(src, dst);
    cudaEventRecord(evJ, s1);

    // concurrent: dense GEMM (tensor cores) on the main (captured) stream
    k_gemm1<<<(NN + 127) / 128, 256, GEMM_SMEM>>>(x, W1);

    // join, then gather chain
    cudaStreamWaitEvent(0, evJ, 0);
    k_gather1h<<<NN / 32, 256>>>(b1, W2);
    k_gather2<<<(NN + 63) / 64, 256>>>(b2, out);
}